// round 9
// baseline (speedup 1.0000x reference)
#include <cuda_runtime.h>

// BoxModelTriples, m-phased for L2 residency (two kernels, AoS partials).
// box: (M=8, B=200000, 2, D=32) f32 -> 64 floats (256 B) per (m, idx) row,
//      z at +0, Z at +128 B. Each m-slab is B*256B = 51.2 MB < 126 MB L2.
// ids: (N, 4) int32. out: (N,) f32.
//
// Kernel 1 (phase): blockIdx.y = m (slow raster dim => slab-phased execution
//   keeps each 51.2 MB slab L2-resident while it is being gathered).
//   warp = 4 queries; per query 8 lanes, 4 dims each. Lane loads float4 z/Z
//   for A,B,C (6x LDG.128), partial side products, xor-reduce over 8 lanes,
//   stores UNWEIGHTED {volA, volAB, volABC, selector} as float4 at
//   g_P[n*8 + m]  (AoS: one 128B line per query). Every line is re-touched
//   by the final m=7 pass => the whole 12.8 MB partial buffer is L2-hot
//   when the reduce kernel starts. Selector rides in .w so reduce never
//   reads ids.
// Kernel 2 (reduce): 1 thread per query reads its 128B line (8 LDG.128,
//   1 L2 hit + 7 L1 hits), weights by smem softmax(w), sums in fixed m
//   order (deterministic), selects by p0.w, stores.

#define TINYF 1.17549435e-38f
#define MAXN  100096

__device__ float4 g_P[8 * MAXN];   // [n * 8 + m] = {volA, volAB, volABC, sel}

__device__ __forceinline__ void side_step(float az, float aZ,
                                          float bz, float bZ,
                                          float cz, float cZ,
                                          float& pA, float& pAB, float& pABC) {
    float a0 = __saturatef(az), a1 = __saturatef(aZ);
    float b0 = __saturatef(bz), b1 = __saturatef(bZ);
    float c0 = __saturatef(cz), c1 = __saturatef(cZ);
    pA *= fmaxf(a1 - a0, 0.0f);
    float z = fmaxf(a0, b0);
    float Z = fminf(a1, b1);
    pAB *= fmaxf(Z - z, 0.0f);
    z = fmaxf(z, c0);
    Z = fminf(Z, c1);
    pABC *= fmaxf(Z - z, 0.0f);
}

__global__ void __launch_bounds__(256)
phase_kernel(const float* __restrict__ box,
             const int* __restrict__ ids,
             int N, int B) {
    int m    = blockIdx.y;                       // slow raster dim -> phased
    int lane = threadIdx.x & 31;
    int warp = threadIdx.x >> 5;                 // 0..7
    int qq   = lane >> 3;                        // query within warp, 0..3
    int d    = lane & 7;                         // dim group, dims [4d, 4d+4)

    int n = (blockIdx.x * 8 + warp) * 4 + qq;
    int nc = n < N ? n : N - 1;                  // clamp loads, predicate store

    int4 id = *(const int4*)(ids + 4 * nc);

    size_t mb = (size_t)m * (size_t)B;
    const float* pAp = box + (mb + (size_t)id.x) * 64 + d * 4;
    const float* pBp = box + (mb + (size_t)id.y) * 64 + d * 4;
    const float* pCp = box + (mb + (size_t)id.z) * 64 + d * 4;

    float4 az = *(const float4*)(pAp);
    float4 aZ = *(const float4*)(pAp + 32);
    float4 bz = *(const float4*)(pBp);
    float4 bZ = *(const float4*)(pBp + 32);
    float4 cz = *(const float4*)(pCp);
    float4 cZ = *(const float4*)(pCp + 32);

    float pA = 1.0f, pAB = 1.0f, pABC = 1.0f;
    side_step(az.x, aZ.x, bz.x, bZ.x, cz.x, cZ.x, pA, pAB, pABC);
    side_step(az.y, aZ.y, bz.y, bZ.y, cz.y, cZ.y, pA, pAB, pABC);
    side_step(az.z, aZ.z, bz.z, bZ.z, cz.z, cZ.z, pA, pAB, pABC);
    side_step(az.w, aZ.w, bz.w, bZ.w, cz.w, cZ.w, pA, pAB, pABC);

    // Product-reduce across the 8 dim-lanes of this query (xor 1, 2, 4).
    #pragma unroll
    for (int off = 1; off <= 4; off <<= 1) {
        pA   *= __shfl_xor_sync(0xFFFFFFFFu, pA,   off);
        pAB  *= __shfl_xor_sync(0xFFFFFFFFu, pAB,  off);
        pABC *= __shfl_xor_sync(0xFFFFFFFFu, pABC, off);
    }

    if (d == 0 && n < N) {
        // selector: 2 = three_cond, 0 = unary, 1 = two_cond
        float sel = (id.y != id.z) ? 2.0f : ((id.x == id.y) ? 0.0f : 1.0f);
        g_P[(size_t)n * 8 + m] = make_float4(pA, pAB, pABC, sel);
    }
}

__global__ void __launch_bounds__(256)
reduce_kernel(const float* __restrict__ w,
              float* __restrict__ out, int N) {
    // Softmax over the 8 weights once per block (smem broadcast).
    __shared__ float s_w[8];
    if (threadIdx.x < 8) {
        float x = w[threadIdx.x];
        float mx = x;
        #pragma unroll
        for (int off = 4; off; off >>= 1)
            mx = fmaxf(mx, __shfl_xor_sync(0x000000FFu, mx, off));
        float e = expf(x - mx);
        float s = e;
        #pragma unroll
        for (int off = 4; off; off >>= 1)
            s += __shfl_xor_sync(0x000000FFu, s, off);
        s_w[threadIdx.x] = e / s;
    }
    __syncthreads();

    int n = blockIdx.x * blockDim.x + threadIdx.x;
    if (n >= N) return;

    // One 128B line per query: 8 float4 partials, L2-hot from the m=7 pass.
    const float4* line = g_P + (size_t)n * 8;
    float sA = 0.0f, sAB = 0.0f, sABC = 0.0f;
    float sel = 0.0f;
    #pragma unroll
    for (int m = 0; m < 8; m++) {
        float4 p = line[m];
        float wm = s_w[m];
        sA   += wm * p.x;
        sAB  += wm * p.y;
        sABC += wm * p.z;
        if (m == 0) sel = p.w;
    }

    float res;
    if (sel == 2.0f) {
        res = (sABC + TINYF) / (sAB + TINYF);      // three_cond
    } else if (sel == 0.0f) {
        res = sA;                                   // unary
    } else {
        res = (sAB + TINYF) / (sA + TINYF);         // two_cond
    }
    out[n] = res;
}

extern "C" void kernel_launch(void* const* d_in, const int* in_sizes, int n_in,
                              void* d_out, int out_size) {
    const float* box = (const float*)d_in[0];
    const float* w   = (const float*)d_in[1];
    const int*   ids = (const int*)d_in[2];
    float*       out = (float*)d_out;

    int Mw = in_sizes[1];                 // 8
    int N  = in_sizes[2] / 4;             // 100000
    int B  = (int)((long long)in_sizes[0] / ((long long)Mw * 64));  // 200000

    // Phase: 32 queries per block (8 warps x 4 queries), m on grid.y (slow).
    int chunks = (N + 31) / 32;
    phase_kernel<<<dim3(chunks, 8), 256>>>(box, ids, N, B);

    // Reduce: 1 thread per query, 256-thread blocks.
    reduce_kernel<<<(N + 255) / 256, 256>>>(w, out, N);
}

// round 10
// speedup vs baseline: 1.0329x; 1.0329x over previous
#include <cuda_runtime.h>

// BoxModelTriples — single persistent kernel, self-phased m-major gather.
// box: (M=8, B=200000, 2, D=32) f32 -> 64 floats (256 B) per (m, idx) row,
//      z at +0, Z at +128 B. Each m-slab is 51.2 MB; L2 = 126 MB holds ~2.
// ids: (N, 4) int32. out: (N,) f32.
//
// Exactly one resident wave: 592 blocks = 4/SM x 148 SMs (enforced via
// __launch_bounds__(256, 4)). Block b owns chunks {b + 592*c : c<6} of 32
// queries each. All blocks loop m = 0..7 in lockstep-ish m-major order, so
// at any instant the chip gathers from (approximately) one 51.2 MB slab ->
// L2-resident, each unique row fetched from DRAM once per slab.
// Per query: 8 lanes x 4 dims; 6x LDG.128 (full 256B row of A, B, C);
// partial side products; xor-reduce over the 8 dim-lanes broadcasts the
// slab volumes to ALL lanes, so every lane accumulates w[m]*vol in
// registers (no smem, no partial buffers, no second kernel).
// Epilogue: lane d==0 applies the mask logic and stores.

#define TINYF 1.17549435e-38f
#define CPB   6   // chunks per block: ceil(3125 / 592)

__device__ __forceinline__ void side_step(float az, float aZ,
                                          float bz, float bZ,
                                          float cz, float cZ,
                                          float& pA, float& pAB, float& pABC) {
    float a0 = __saturatef(az), a1 = __saturatef(aZ);
    float b0 = __saturatef(bz), b1 = __saturatef(bZ);
    float c0 = __saturatef(cz), c1 = __saturatef(cZ);
    pA *= fmaxf(a1 - a0, 0.0f);
    float z = fmaxf(a0, b0);
    float Z = fminf(a1, b1);
    pAB *= fmaxf(Z - z, 0.0f);
    z = fmaxf(z, c0);
    Z = fminf(Z, c1);
    pABC *= fmaxf(Z - z, 0.0f);
}

__global__ void __launch_bounds__(256, 4)
fused_phased_kernel(const float* __restrict__ box,
                    const float* __restrict__ w,
                    const int* __restrict__ ids,
                    float* __restrict__ out,
                    int N, int B) {
    // Softmax over the 8 weights once per block (smem broadcast).
    __shared__ float s_w[8];
    if (threadIdx.x < 8) {
        float x = w[threadIdx.x];
        float mx = x;
        #pragma unroll
        for (int off = 4; off; off >>= 1)
            mx = fmaxf(mx, __shfl_xor_sync(0x000000FFu, mx, off));
        float e = expf(x - mx);
        float s = e;
        #pragma unroll
        for (int off = 4; off; off >>= 1)
            s += __shfl_xor_sync(0x000000FFu, s, off);
        s_w[threadIdx.x] = e / s;
    }
    __syncthreads();

    int lane = threadIdx.x & 31;
    int warp = threadIdx.x >> 5;                 // 0..7
    int qq   = lane >> 3;                        // query within warp, 0..3
    int d    = lane & 7;                         // dim group, dims [4d, 4d+4)

    float sA[CPB], sAB[CPB], sABC[CPB];
    #pragma unroll
    for (int c = 0; c < CPB; c++) { sA[c] = 0.0f; sAB[c] = 0.0f; sABC[c] = 0.0f; }

    for (int m = 0; m < 8; m++) {
        float wm = s_w[m];
        size_t mb = (size_t)m * (size_t)B;

        #pragma unroll
        for (int c = 0; c < CPB; c++) {
            int chunk = blockIdx.x + c * gridDim.x;     // strided for balance
            int n = chunk * 32 + warp * 4 + qq;
            int nc = n < N ? n : N - 1;                 // clamp (redundant work)

            int4 id = *(const int4*)(ids + 4 * nc);     // L2-hot after pass 0

            const float* pAp = box + (mb + (size_t)id.x) * 64 + d * 4;
            const float* pBp = box + (mb + (size_t)id.y) * 64 + d * 4;
            const float* pCp = box + (mb + (size_t)id.z) * 64 + d * 4;

            float4 az = *(const float4*)(pAp);
            float4 aZ = *(const float4*)(pAp + 32);
            float4 bz = *(const float4*)(pBp);
            float4 bZ = *(const float4*)(pBp + 32);
            float4 cz = *(const float4*)(pCp);
            float4 cZ = *(const float4*)(pCp + 32);

            float pA = 1.0f, pAB = 1.0f, pABC = 1.0f;
            side_step(az.x, aZ.x, bz.x, bZ.x, cz.x, cZ.x, pA, pAB, pABC);
            side_step(az.y, aZ.y, bz.y, bZ.y, cz.y, cZ.y, pA, pAB, pABC);
            side_step(az.z, aZ.z, bz.z, bZ.z, cz.z, cZ.z, pA, pAB, pABC);
            side_step(az.w, aZ.w, bz.w, bZ.w, cz.w, cZ.w, pA, pAB, pABC);

            // Product-reduce across 8 dim-lanes; result broadcast to all lanes.
            #pragma unroll
            for (int off = 1; off <= 4; off <<= 1) {
                pA   *= __shfl_xor_sync(0xFFFFFFFFu, pA,   off);
                pAB  *= __shfl_xor_sync(0xFFFFFFFFu, pAB,  off);
                pABC *= __shfl_xor_sync(0xFFFFFFFFu, pABC, off);
            }

            sA[c]   = fmaf(wm, pA,   sA[c]);
            sAB[c]  = fmaf(wm, pAB,  sAB[c]);
            sABC[c] = fmaf(wm, pABC, sABC[c]);
        }
        __syncthreads();   // bound intra-block drift between slab passes
    }

    // Epilogue: mask logic + store, one lane per query.
    #pragma unroll
    for (int c = 0; c < CPB; c++) {
        int chunk = blockIdx.x + c * gridDim.x;
        int n = chunk * 32 + warp * 4 + qq;
        if (d == 0 && n < N) {
            int4 id = *(const int4*)(ids + 4 * n);
            float res;
            if (id.y != id.z) {
                res = (sABC[c] + TINYF) / (sAB[c] + TINYF);   // three_cond
            } else if (id.x == id.y) {
                res = sA[c];                                   // unary
            } else {
                res = (sAB[c] + TINYF) / (sA[c] + TINYF);      // two_cond
            }
            out[n] = res;
        }
    }
}

extern "C" void kernel_launch(void* const* d_in, const int* in_sizes, int n_in,
                              void* d_out, int out_size) {
    const float* box = (const float*)d_in[0];
    const float* w   = (const float*)d_in[1];
    const int*   ids = (const int*)d_in[2];
    float*       out = (float*)d_out;

    int Mw = in_sizes[1];                 // 8
    int N  = in_sizes[2] / 4;             // 100000
    int B  = (int)((long long)in_sizes[0] / ((long long)Mw * 64));  // 200000

    // One resident wave: 4 blocks/SM x 148 SMs.
    fused_phased_kernel<<<592, 256>>>(box, w, ids, out, N, B);
}